// round 15
// baseline (speedup 1.0000x reference)
#include <cuda_runtime.h>
#include <cuda_fp16.h>
#include <cstdint>

// Conv (32,64,64,128) NHWC fp32 * w(256,1152) + b -> (32,62,62,256) fp32
// via Winograd F(2x2,3x3), output transform fused into the GEMM.
// R15 = R13 + (a) full-K (128) pipeline stages: 1 wait + 1 sync per pos,
//             (b) rolled pos loop (small I$ footprint), runtime +-1 fold.
// MACs: 16 * 30848 * 256 * 128 = 16.2G

#define NIMG 32
#define HI 64
#define WI 64
#define CI 128
#define FO 256
#define HOUT 62
#define NT 31
#define MW 30752       // 32*31*31
#define MPAD 30848     // 241*128
#define NPOS 16

__device__ __align__(16) __half g_wT[(size_t)NPOS * FO * CI];     // [pos][f][c]
__device__ __align__(16) __half g_inT[(size_t)NPOS * MPAD * CI];  // [pos][m'][c]

// ---------------- common helpers ----------------
__device__ __forceinline__ uint32_t smem_u32(const void* p) {
    uint32_t a;
    asm("{ .reg .u64 t; cvta.to.shared.u64 t, %1; cvt.u32.u64 %0, t; }"
        : "=r"(a) : "l"(p));
    return a;
}
__device__ __forceinline__ void cpa16(uint32_t dst, const void* src) {
    asm volatile("cp.async.cg.shared.global [%0], [%1], 16;"
                 :: "r"(dst), "l"(src));
}
#define CP_COMMIT() asm volatile("cp.async.commit_group;" ::: "memory")
#define CP_WAIT0()  asm volatile("cp.async.wait_group 0;" ::: "memory")

__device__ __forceinline__ void ldm4(uint32_t* r, uint32_t a) {
    asm volatile("ldmatrix.sync.aligned.m8n8.x4.shared.b16 {%0,%1,%2,%3}, [%4];"
                 : "=r"(r[0]), "=r"(r[1]), "=r"(r[2]), "=r"(r[3]) : "r"(a));
}
__device__ __forceinline__ void mma16816(float* c, const uint32_t* a,
                                         uint32_t b0, uint32_t b1) {
    asm volatile(
        "mma.sync.aligned.m16n8k16.row.col.f32.f16.f16.f32 "
        "{%0,%1,%2,%3}, {%4,%5,%6,%7}, {%8,%9}, {%0,%1,%2,%3};"
        : "+f"(c[0]), "+f"(c[1]), "+f"(c[2]), "+f"(c[3])
        : "r"(a[0]), "r"(a[1]), "r"(a[2]), "r"(a[3]), "r"(b0), "r"(b1));
}

__device__ __forceinline__ float4 f4add(float4 a, float4 b) {
    return make_float4(a.x + b.x, a.y + b.y, a.z + b.z, a.w + b.w);
}
__device__ __forceinline__ float4 f4sub(float4 a, float4 b) {
    return make_float4(a.x - b.x, a.y - b.y, a.z - b.z, a.w - b.w);
}
__device__ __forceinline__ uint2 pack4h(float4 v) {
    __half2 p0 = __floats2half2_rn(v.x, v.y);
    __half2 p1 = __floats2half2_rn(v.z, v.w);
    uint2 r;
    r.x = *reinterpret_cast<uint32_t*>(&p0);
    r.y = *reinterpret_cast<uint32_t*>(&p1);
    return r;
}

// ---------------- K1: input + weight transforms (R9-validated) ----------------
#define K1_IN_BLOCKS 3844
#define K1_W_BLOCKS  128

__global__ __launch_bounds__(256)
void winograd_transform(const float* __restrict__ in, const float* __restrict__ w) {
    const int b = blockIdx.x;
    if (b < K1_IN_BLOCKS) {
        const int gt = b * 256 + threadIdx.x;
        const int mp = gt >> 5;
        const int c0 = (gt & 31) * 4;
        const int n  = mp / (NT * NT);
        const int r  = mp - n * (NT * NT);
        const int th = r / NT;
        const int tw = r - th * NT;
        const float* base = in + (((long)(n * HI + 2 * th)) * WI + 2 * tw) * CI + c0;

        float4 t[4][4];
#pragma unroll
        for (int q = 0; q < 4; q++) {
            float4 d0 = *reinterpret_cast<const float4*>(base + (0 * WI + q) * CI);
            float4 d1 = *reinterpret_cast<const float4*>(base + (1 * WI + q) * CI);
            float4 d2 = *reinterpret_cast<const float4*>(base + (2 * WI + q) * CI);
            float4 d3 = *reinterpret_cast<const float4*>(base + (3 * WI + q) * CI);
            t[0][q] = f4sub(d0, d2);
            t[1][q] = f4add(d1, d2);
            t[2][q] = f4sub(d2, d1);
            t[3][q] = f4sub(d1, d3);
        }
        __half* dst0 = g_inT + (long)mp * CI + c0;
#pragma unroll
        for (int i = 0; i < 4; i++) {
            float4 a0 = f4sub(t[i][0], t[i][2]);
            float4 a1 = f4add(t[i][1], t[i][2]);
            float4 a2 = f4sub(t[i][2], t[i][1]);
            float4 a3 = f4sub(t[i][1], t[i][3]);
            const long ps = (long)MPAD * CI;
            *reinterpret_cast<uint2*>(dst0 + (long)(4 * i + 0) * ps) = pack4h(a0);
            *reinterpret_cast<uint2*>(dst0 + (long)(4 * i + 1) * ps) = pack4h(a1);
            *reinterpret_cast<uint2*>(dst0 + (long)(4 * i + 2) * ps) = pack4h(a2);
            *reinterpret_cast<uint2*>(dst0 + (long)(4 * i + 3) * ps) = pack4h(a3);
        }
    } else {
        const int wt = (b - K1_IN_BLOCKS) * 256 + threadIdx.x;
        const int f = wt >> 7;
        const int c = wt & 127;
        float g[3][3];
#pragma unroll
        for (int i = 0; i < 3; i++)
#pragma unroll
            for (int j = 0; j < 3; j++)
                g[i][j] = w[(long)f * 1152 + (i * 3 + j) * CI + c];
        float u[4][3];
#pragma unroll
        for (int k = 0; k < 3; k++) {
            u[0][k] = g[0][k];
            u[1][k] = 0.5f * (g[0][k] + g[1][k] + g[2][k]);
            u[2][k] = 0.5f * (g[0][k] - g[1][k] + g[2][k]);
            u[3][k] = g[2][k];
        }
        __half* dst = g_wT + (long)f * CI + c;
#pragma unroll
        for (int i = 0; i < 4; i++) {
            float v0 = u[i][0];
            float v1 = 0.5f * (u[i][0] + u[i][1] + u[i][2]);
            float v2 = 0.5f * (u[i][0] - u[i][1] + u[i][2]);
            float v3 = u[i][2];
            const long ps = (long)FO * CI;
            dst[(long)(4 * i + 0) * ps] = __float2half(v0);
            dst[(long)(4 * i + 1) * ps] = __float2half(v1);
            dst[(long)(4 * i + 2) * ps] = __float2half(v2);
            dst[(long)(4 * i + 3) * ps] = __float2half(v3);
        }
    }
}

// ---------------- K2: fused GEMM + output transform ----------------
// CTA tile: 128 m' x 32 f; 8 warps, each warp 16 m-rows x 32 f.
// Full K=128 per stage; 2-stage double buffer (80KB -> 2 CTAs/SM).
// Rows are 256B = 16 x 16B chunks; swizzle: chunk c -> c ^ (row & 7).
#define FSTAGE 40960               // A 32KB + B 8KB
#define FSMEM (2 * FSTAGE)         // 81920
#define OFF_B 32768

__device__ __forceinline__ void f_prefetch(uint32_t sb, int pos,
                                           int m_base, int f_base, int tid) {
    const uint32_t st = sb + (pos & 1) * FSTAGE;
    // A: 128 rows x 128 halves (256B/row); 2 threads/row, 8 x 16B each
    {
        const int row = tid >> 1;
        const int h   = tid & 1;
        const __half* asrc = g_inT + ((long)pos * MPAD + m_base + row) * CI;
#pragma unroll
        for (int j = 0; j < 8; j++) {
            const int c  = h * 8 + j;
            const int cs = c ^ (row & 7);
            cpa16(st + row * 256 + cs * 16, asrc + c * 8);
        }
    }
    // B: 32 rows x 128 halves; 8 threads/row, 2 x 16B each
    {
        const int row = tid >> 3;
        const __half* bsrc = g_wT + ((long)pos * FO + f_base + row) * CI;
#pragma unroll
        for (int j = 0; j < 2; j++) {
            const int c  = (tid & 7) * 2 + j;
            const int cs = c ^ (row & 7);
            cpa16(st + OFF_B + row * 256 + cs * 16, bsrc + c * 8);
        }
    }
}

__global__ __launch_bounds__(256, 2)
void winograd_fused(const float* __restrict__ bias, float* __restrict__ out) {
    extern __shared__ char smem[];
    const uint32_t sb = smem_u32(smem);
    const int tid  = threadIdx.x;
    const int lane = tid & 31;
    const int wid  = tid >> 5;           // 0..7 -> 16-row slab
    const int f_base = blockIdx.x * 32;  // 8 tiles  (fast dim -> co-resident)
    const int m_base = blockIdx.y * 128; // 241 tiles

    // y accumulators: [a][b][nb][4], init to bias
    float y[2][2][4][4];
#pragma unroll
    for (int nb = 0; nb < 4; nb++) {
        const int f = f_base + nb * 8 + (lane & 3) * 2;
        const float2 bv = *reinterpret_cast<const float2*>(bias + f);
#pragma unroll
        for (int a = 0; a < 2; a++)
#pragma unroll
            for (int b = 0; b < 2; b++) {
                y[a][b][nb][0] = bv.x; y[a][b][nb][1] = bv.y;
                y[a][b][nb][2] = bv.x; y[a][b][nb][3] = bv.y;
            }
    }

    f_prefetch(sb, 0, m_base, f_base, tid);
    CP_COMMIT();

#pragma unroll 1
    for (int pos = 0; pos < NPOS; pos++) {
        CP_WAIT0();          // this pos's stage complete
        __syncthreads();     // all warps past pos-1 compute (its buffer free)

        if (pos + 1 < NPOS) f_prefetch(sb, pos + 1, m_base, f_base, tid);
        CP_COMMIT();

        const uint32_t st = sb + (pos & 1) * FSTAGE;
        float acc[4][4];
#pragma unroll
        for (int nb = 0; nb < 4; nb++)
#pragma unroll
            for (int k = 0; k < 4; k++) acc[nb][k] = 0.0f;

#pragma unroll
        for (int s = 0; s < 8; s++) {        // eight k16 steps (K=128)
            const int c  = s * 2 + (lane >> 4);
            const int rl = lane & 15;
            uint32_t ah[4], bh[2][4];
            {
                const int row = wid * 16 + rl;
                const int cs  = c ^ (row & 7);
                ldm4(ah, st + row * 256 + cs * 16);
            }
#pragma unroll
            for (int i = 0; i < 2; i++) {
                const int row = i * 16 + rl;
                const int cs  = c ^ (row & 7);
                ldm4(bh[i], st + OFF_B + row * 256 + cs * 16);
            }
#pragma unroll
            for (int i = 0; i < 2; i++)
#pragma unroll
                for (int h = 0; h < 2; h++)
                    mma16816(acc[i * 2 + h], ah, bh[i][h], bh[i][h + 2]);
        }

        // fold into y with runtime +-1/0 coefficients (exact)
        const int pi = pos >> 2, pj = pos & 3;
        const float ca0 = (pi != 3) ? 1.f : 0.f;
        const float ca1 = (pi == 0) ? 0.f : ((pi == 1) ? 1.f : -1.f);
        const float cb0 = (pj != 3) ? 1.f : 0.f;
        const float cb1 = (pj == 0) ? 0.f : ((pj == 1) ? 1.f : -1.f);
        const float c00 = ca0 * cb0, c01 = ca0 * cb1;
        const float c10 = ca1 * cb0, c11 = ca1 * cb1;
#pragma unroll
        for (int nb = 0; nb < 4; nb++)
#pragma unroll
            for (int k = 0; k < 4; k++) {
                const float v = acc[nb][k];
                y[0][0][nb][k] += c00 * v;
                y[0][1][nb][k] += c01 * v;
                y[1][0][nb][k] += c10 * v;
                y[1][1][nb][k] += c11 * v;
            }
    }

    // ---- store: decode m' -> (n, th, tw), write 2x2 outputs ----
#pragma unroll
    for (int rr = 0; rr < 2; rr++) {
        const int mp = m_base + wid * 16 + (lane >> 2) + rr * 8;
        if (mp >= MW) continue;
        const int n  = mp / (NT * NT);
        const int r  = mp - n * (NT * NT);
        const int th = r / NT;
        const int tw = r - th * NT;
#pragma unroll
        for (int a = 0; a < 2; a++)
#pragma unroll
            for (int b = 0; b < 2; b++) {
                float* dst = out + (((long)(n * HOUT + 2 * th + a)) * HOUT
                                    + (2 * tw + b)) * FO;
#pragma unroll
                for (int nb = 0; nb < 4; nb++) {
                    const int f = f_base + nb * 8 + (lane & 3) * 2;
                    float2 v;
                    v.x = y[a][b][nb][rr * 2 + 0];
                    v.y = y[a][b][nb][rr * 2 + 1];
                    *reinterpret_cast<float2*>(dst + f) = v;
                }
            }
    }
}

extern "C" void kernel_launch(void* const* d_in, const int* in_sizes, int n_in,
                              void* d_out, int out_size) {
    const float* in   = (const float*)d_in[0];
    const float* w    = (const float*)d_in[1];
    const float* bias = (const float*)d_in[2];
    float* out        = (float*)d_out;

    winograd_transform<<<K1_IN_BLOCKS + K1_W_BLOCKS, 256>>>(in, w);

    cudaFuncSetAttribute(winograd_fused,
                         cudaFuncAttributeMaxDynamicSharedMemorySize, FSMEM);
    dim3 grid(8, MPAD / 128);   // (8 f-tiles, 241 m-tiles) — f fastest
    winograd_fused<<<grid, 256, FSMEM>>>(bias, out);
}

// round 16
// speedup vs baseline: 1.5764x; 1.5764x over previous
#include <cuda_runtime.h>
#include <cuda_fp16.h>
#include <cstdint>

// Conv (32,64,64,128) NHWC fp32 * w(256,1152) + b -> (32,62,62,256) fp32
// via Winograd F(2x2,3x3), output transform fused into the GEMM:
//   y(a,b) = bias + sum_p AT[a][p>>2]*AT[b][p&3] * (A~_p . W~_p^T)
// R16 = R13 (validated 227.7us) + weight-transform blocks scheduled first
//       + evict-first (.cs) output stores to protect L2 A-plane reuse.
// MACs: 16 * 30848 * 256 * 128 = 16.2G

#define NIMG 32
#define HI 64
#define WI 64
#define CI 128
#define FO 256
#define HOUT 62
#define NT 31
#define MW 30752       // 32*31*31
#define MPAD 30848     // 241*128
#define NPOS 16

__device__ __align__(16) __half g_wT[(size_t)NPOS * FO * CI];     // [pos][f][c]
__device__ __align__(16) __half g_inT[(size_t)NPOS * MPAD * CI];  // [pos][m'][c]

// ---------------- common helpers ----------------
__device__ __forceinline__ uint32_t smem_u32(const void* p) {
    uint32_t a;
    asm("{ .reg .u64 t; cvta.to.shared.u64 t, %1; cvt.u32.u64 %0, t; }"
        : "=r"(a) : "l"(p));
    return a;
}
__device__ __forceinline__ void cpa16(uint32_t dst, const void* src) {
    asm volatile("cp.async.cg.shared.global [%0], [%1], 16;"
                 :: "r"(dst), "l"(src));
}
#define CP_COMMIT() asm volatile("cp.async.commit_group;" ::: "memory")
#define CP_WAIT1()  asm volatile("cp.async.wait_group 1;" ::: "memory")
#define CP_WAIT0()  asm volatile("cp.async.wait_group 0;" ::: "memory")

__device__ __forceinline__ void ldm4(uint32_t* r, uint32_t a) {
    asm volatile("ldmatrix.sync.aligned.m8n8.x4.shared.b16 {%0,%1,%2,%3}, [%4];"
                 : "=r"(r[0]), "=r"(r[1]), "=r"(r[2]), "=r"(r[3]) : "r"(a));
}
__device__ __forceinline__ void mma16816(float* c, const uint32_t* a,
                                         uint32_t b0, uint32_t b1) {
    asm volatile(
        "mma.sync.aligned.m16n8k16.row.col.f32.f16.f16.f32 "
        "{%0,%1,%2,%3}, {%4,%5,%6,%7}, {%8,%9}, {%0,%1,%2,%3};"
        : "+f"(c[0]), "+f"(c[1]), "+f"(c[2]), "+f"(c[3])
        : "r"(a[0]), "r"(a[1]), "r"(a[2]), "r"(a[3]), "r"(b0), "r"(b1));
}
__device__ __forceinline__ void stcs8(float* p, float2 v) {
    asm volatile("st.global.cs.v2.f32 [%0], {%1, %2};"
                 :: "l"(p), "f"(v.x), "f"(v.y) : "memory");
}

__device__ __forceinline__ float4 f4add(float4 a, float4 b) {
    return make_float4(a.x + b.x, a.y + b.y, a.z + b.z, a.w + b.w);
}
__device__ __forceinline__ float4 f4sub(float4 a, float4 b) {
    return make_float4(a.x - b.x, a.y - b.y, a.z - b.z, a.w - b.w);
}
__device__ __forceinline__ uint2 pack4h(float4 v) {
    __half2 p0 = __floats2half2_rn(v.x, v.y);
    __half2 p1 = __floats2half2_rn(v.z, v.w);
    uint2 r;
    r.x = *reinterpret_cast<uint32_t*>(&p0);
    r.y = *reinterpret_cast<uint32_t*>(&p1);
    return r;
}

// ---------------- K1: weight + input transforms ----------------
#define K1_IN_BLOCKS 3844          // 30752 m' * 32 cgroups / 256
#define K1_W_BLOCKS  128           // 256 f * 128 c / 256

__global__ __launch_bounds__(256)
void winograd_transform(const float* __restrict__ in, const float* __restrict__ w) {
    const int b = blockIdx.x;
    if (b < K1_W_BLOCKS) {
        // ---- weight transform FIRST (divergent blocks scheduled early) ----
        const int wt = b * 256 + threadIdx.x;   // < 32768
        const int f = wt >> 7;
        const int c = wt & 127;
        float g[3][3];
#pragma unroll
        for (int i = 0; i < 3; i++)
#pragma unroll
            for (int j = 0; j < 3; j++)
                g[i][j] = w[(long)f * 1152 + (i * 3 + j) * CI + c];
        float u[4][3];
#pragma unroll
        for (int k = 0; k < 3; k++) {
            u[0][k] = g[0][k];
            u[1][k] = 0.5f * (g[0][k] + g[1][k] + g[2][k]);
            u[2][k] = 0.5f * (g[0][k] - g[1][k] + g[2][k]);
            u[3][k] = g[2][k];
        }
        __half* dst = g_wT + (long)f * CI + c;
#pragma unroll
        for (int i = 0; i < 4; i++) {
            float v0 = u[i][0];
            float v1 = 0.5f * (u[i][0] + u[i][1] + u[i][2]);
            float v2 = 0.5f * (u[i][0] - u[i][1] + u[i][2]);
            float v3 = u[i][2];
            const long ps = (long)FO * CI;
            dst[(long)(4 * i + 0) * ps] = __float2half(v0);
            dst[(long)(4 * i + 1) * ps] = __float2half(v1);
            dst[(long)(4 * i + 2) * ps] = __float2half(v2);
            dst[(long)(4 * i + 3) * ps] = __float2half(v3);
        }
    } else {
        // ---- input transform: A~ = B^T d B per (m', 4 channels) ----
        const int gt = (b - K1_W_BLOCKS) * 256 + threadIdx.x;
        const int mp = gt >> 5;
        const int c0 = (gt & 31) * 4;
        const int n  = mp / (NT * NT);
        const int r  = mp - n * (NT * NT);
        const int th = r / NT;
        const int tw = r - th * NT;
        const float* base = in + (((long)(n * HI + 2 * th)) * WI + 2 * tw) * CI + c0;

        float4 t[4][4];
#pragma unroll
        for (int q = 0; q < 4; q++) {
            float4 d0 = *reinterpret_cast<const float4*>(base + (0 * WI + q) * CI);
            float4 d1 = *reinterpret_cast<const float4*>(base + (1 * WI + q) * CI);
            float4 d2 = *reinterpret_cast<const float4*>(base + (2 * WI + q) * CI);
            float4 d3 = *reinterpret_cast<const float4*>(base + (3 * WI + q) * CI);
            t[0][q] = f4sub(d0, d2);
            t[1][q] = f4add(d1, d2);
            t[2][q] = f4sub(d2, d1);
            t[3][q] = f4sub(d1, d3);
        }
        __half* dst0 = g_inT + (long)mp * CI + c0;
#pragma unroll
        for (int i = 0; i < 4; i++) {
            float4 a0 = f4sub(t[i][0], t[i][2]);
            float4 a1 = f4add(t[i][1], t[i][2]);
            float4 a2 = f4sub(t[i][2], t[i][1]);
            float4 a3 = f4sub(t[i][1], t[i][3]);
            const long ps = (long)MPAD * CI;
            *reinterpret_cast<uint2*>(dst0 + (long)(4 * i + 0) * ps) = pack4h(a0);
            *reinterpret_cast<uint2*>(dst0 + (long)(4 * i + 1) * ps) = pack4h(a1);
            *reinterpret_cast<uint2*>(dst0 + (long)(4 * i + 2) * ps) = pack4h(a2);
            *reinterpret_cast<uint2*>(dst0 + (long)(4 * i + 3) * ps) = pack4h(a3);
        }
    }
}

// ---------------- K2: fused GEMM + output transform (R13-validated) ----------
// CTA tile: 128 m' x 32 f; 8 warps, each warp 16 m-rows x 32 f.
// Loops pos 0..15; per pos K=128 as 2 chunks of 64; 3-stage cp.async pipeline.
#define FSTAGE 20480               // A 16KB + B 4KB
#define FSMEM (3 * FSTAGE)         // 61440 -> 2 CTAs/SM
#define OFF_B 16384

__device__ __forceinline__ void f_prefetch(uint32_t sb, int stage, int fc,
                                           int m_base, int f_base, int tid) {
    const int pos   = fc >> 1;
    const int khalf = (fc & 1) * 64;
    const uint32_t st = sb + stage * FSTAGE;
    // A: 128 rows x 64 halves; 2 threads/row, 4 x 16B each
    {
        const int row = tid >> 1;
        const int h   = tid & 1;
        const __half* asrc = g_inT + ((long)pos * MPAD + m_base + row) * CI + khalf;
#pragma unroll
        for (int j = 0; j < 4; j++) {
            const int c  = h * 4 + j;
            const int cs = c ^ (row & 7);
            cpa16(st + row * 128 + cs * 16, asrc + c * 8);
        }
    }
    // B: 32 rows x 64 halves; 8 threads/row, 1 x 16B each
    {
        const int row = tid >> 3;
        const int c   = tid & 7;
        const int cs  = c ^ (row & 7);
        const __half* bsrc = g_wT + ((long)pos * FO + f_base + row) * CI + khalf;
        cpa16(st + OFF_B + row * 128 + cs * 16, bsrc + c * 8);
    }
}

__global__ __launch_bounds__(256, 2)
void winograd_fused(const float* __restrict__ bias, float* __restrict__ out) {
    extern __shared__ char smem[];
    const uint32_t sb = smem_u32(smem);
    const int tid  = threadIdx.x;
    const int lane = tid & 31;
    const int wid  = tid >> 5;           // 0..7 -> 16-row slab
    const int f_base = blockIdx.x * 32;  // 8 tiles  (fast dim -> co-resident)
    const int m_base = blockIdx.y * 128; // 241 tiles

    // y accumulators: [a][b][nb][4], init to bias
    float y[2][2][4][4];
#pragma unroll
    for (int nb = 0; nb < 4; nb++) {
        const int f = f_base + nb * 8 + (lane & 3) * 2;
        const float2 bv = *reinterpret_cast<const float2*>(bias + f);
#pragma unroll
        for (int a = 0; a < 2; a++)
#pragma unroll
            for (int b = 0; b < 2; b++) {
                y[a][b][nb][0] = bv.x; y[a][b][nb][1] = bv.y;
                y[a][b][nb][2] = bv.x; y[a][b][nb][3] = bv.y;
            }
    }

    f_prefetch(sb, 0, 0, m_base, f_base, tid); CP_COMMIT();
    f_prefetch(sb, 1, 1, m_base, f_base, tid); CP_COMMIT();

    const float AT0[4] = {1.f, 1.f, 1.f, 0.f};
    const float AT1[4] = {0.f, 1.f, -1.f, -1.f};

#pragma unroll
    for (int pos = 0; pos < NPOS; pos++) {
        float acc[4][4];
#pragma unroll
        for (int nb = 0; nb < 4; nb++)
#pragma unroll
            for (int k = 0; k < 4; k++) acc[nb][k] = 0.0f;

#pragma unroll
        for (int half = 0; half < 2; half++) {
            const int fc = pos * 2 + half;
            CP_WAIT1();
            __syncthreads();
            if (fc < 2 * NPOS - 2)
                f_prefetch(sb, (fc + 2) % 3, fc + 2, m_base, f_base, tid);
            CP_COMMIT();

            const uint32_t st = sb + (fc % 3) * FSTAGE;
#pragma unroll
            for (int s = 0; s < 4; s++) {
                uint32_t ah[4], bh[2][4];
                const int c  = s * 2 + (lane >> 4);
                const int rl = lane & 15;
                {
                    const int row = wid * 16 + rl;
                    const int cs  = c ^ (row & 7);
                    ldm4(ah, st + row * 128 + cs * 16);
                }
#pragma unroll
                for (int i = 0; i < 2; i++) {
                    const int row = i * 16 + rl;
                    const int cs  = c ^ (row & 7);
                    ldm4(bh[i], st + OFF_B + row * 128 + cs * 16);
                }
#pragma unroll
                for (int i = 0; i < 2; i++)
#pragma unroll
                    for (int h = 0; h < 2; h++)
                        mma16816(acc[i * 2 + h], ah, bh[i][h], bh[i][h + 2]);
            }
        }

        // fold this pos into y with compile-time +-1 coefficients
        const int pi = pos >> 2, pj = pos & 3;
#pragma unroll
        for (int a = 0; a < 2; a++) {
            const float ca = (a == 0) ? AT0[pi] : AT1[pi];
            if (ca == 0.f) continue;
#pragma unroll
            for (int b = 0; b < 2; b++) {
                const float cb = (b == 0) ? AT0[pj] : AT1[pj];
                if (cb == 0.f) continue;
                const float cc = ca * cb;
#pragma unroll
                for (int nb = 0; nb < 4; nb++)
#pragma unroll
                    for (int k = 0; k < 4; k++)
                        y[a][b][nb][k] += cc * acc[nb][k];
            }
        }
    }
    CP_WAIT0();

    // ---- store: decode m' -> (n, th, tw), write 2x2 outputs (evict-first) ----
#pragma unroll
    for (int rr = 0; rr < 2; rr++) {
        const int mp = m_base + wid * 16 + (lane >> 2) + rr * 8;
        if (mp >= MW) continue;
        const int n  = mp / (NT * NT);
        const int r  = mp - n * (NT * NT);
        const int th = r / NT;
        const int tw = r - th * NT;
#pragma unroll
        for (int a = 0; a < 2; a++)
#pragma unroll
            for (int b = 0; b < 2; b++) {
                float* dst = out + (((long)(n * HOUT + 2 * th + a)) * HOUT
                                    + (2 * tw + b)) * FO;
#pragma unroll
                for (int nb = 0; nb < 4; nb++) {
                    const int f = f_base + nb * 8 + (lane & 3) * 2;
                    float2 v;
                    v.x = y[a][b][nb][rr * 2 + 0];
                    v.y = y[a][b][nb][rr * 2 + 1];
                    stcs8(dst + f, v);
                }
            }
    }
}

extern "C" void kernel_launch(void* const* d_in, const int* in_sizes, int n_in,
                              void* d_out, int out_size) {
    const float* in   = (const float*)d_in[0];
    const float* w    = (const float*)d_in[1];
    const float* bias = (const float*)d_in[2];
    float* out        = (float*)d_out;

    winograd_transform<<<K1_IN_BLOCKS + K1_W_BLOCKS, 256>>>(in, w);

    cudaFuncSetAttribute(winograd_fused,
                         cudaFuncAttributeMaxDynamicSharedMemorySize, FSMEM);
    dim3 grid(8, MPAD / 128);   // (8 f-tiles, 241 m-tiles) — f fastest
    winograd_fused<<<grid, 256, FSMEM>>>(bias, out);
}